// round 10
// baseline (speedup 1.0000x reference)
#include <cuda_runtime.h>
#include <math.h>
#include <stdint.h>

#define B_   32
#define T_   2048
#define D_   512
#define H_   512
#define G4_  2048
#define NBLK 128
#define XS_  34
#define HQS  132        // quarter buffer row stride (floats); 16B-aligned rows

// ---------------- device scratch ----------------------------------------------
__device__ float g_xproj[(size_t)T_ * G4_ * B_];   // [t][g][b]
__device__ __align__(16) float g_h[2][B_ * H_];    // [b][j]  double-buffered
__device__ unsigned g_epoch;
__device__ unsigned g_flags[NBLK * 64];            // one flag per 256B line

// ---------------- helpers -------------------------------------------------------
__device__ __forceinline__ unsigned long long pack2(float lo, float hi) {
    unsigned long long r;
    asm("mov.b64 %0, {%1, %2};" : "=l"(r) : "f"(lo), "f"(hi));
    return r;
}
__device__ __forceinline__ void fma2(unsigned long long& d,
                                     unsigned long long a, unsigned long long b) {
    asm("fma.rn.f32x2 %0, %1, %2, %0;" : "+l"(d) : "l"(a), "l"(b));
}
__device__ __forceinline__ void unpack2(unsigned long long v, float& lo, float& hi) {
    asm("mov.b64 {%0, %1}, %2;" : "=f"(lo), "=f"(hi) : "l"(v));
}
__device__ __forceinline__ unsigned ld_acq(const unsigned* p) {
    unsigned v;
    asm volatile("ld.acquire.gpu.u32 %0, [%1];" : "=r"(v) : "l"(p) : "memory");
    return v;
}
__device__ __forceinline__ void st_rel(unsigned* p, unsigned v) {
    asm volatile("st.release.gpu.u32 [%0], %1;" :: "l"(p), "r"(v) : "memory");
}
__device__ __forceinline__ uint32_t smem_u32(const void* p) {
    return (uint32_t)__cvta_generic_to_shared(p);
}
__device__ __forceinline__ void cp_async16(uint32_t dst, const float* src) {
    asm volatile("cp.async.cg.shared.global [%0], [%1], 16;"
                 :: "r"(dst), "l"(src) : "memory");
}
__device__ __forceinline__ void cp_commit() {
    asm volatile("cp.async.commit_group;" ::: "memory");
}
__device__ __forceinline__ void cp_wait0() {
    asm volatile("cp.async.wait_group 0;" ::: "memory");
}
__device__ __forceinline__ float tanh_approx(float x) {
    float y;
    asm("tanh.approx.f32 %0, %1;" : "=f"(y) : "f"(x));
    return y;
}
__device__ __forceinline__ float sigmoid_fast(float x) {
    return fmaf(tanh_approx(0.5f * x), 0.5f, 0.5f);
}

__global__ void lstm_epoch_kernel() {
    if (threadIdx.x == 0) g_epoch = g_epoch + 1u;
}

// ---------------- Phase 1: x_proj (unchanged) ----------------------------------
__global__ void __launch_bounds__(128, 4) lstm_xproj_kernel(
    const float* __restrict__ input,
    const float* __restrict__ W_ih,
    const float* __restrict__ b_ih,
    const float* __restrict__ b_hh)
{
    __shared__ float ws[128 * 36];
    __shared__ float xs[32 * XS_];

    const int t   = blockIdx.x;
    const int g0  = blockIdx.y * 128;
    const int tid = threadIdx.x;
    const int gg  = tid >> 3;
    const int bg  = tid & 7;

    unsigned long long acc2[16];
#pragma unroll
    for (int v = 0; v < 16; v++) acc2[v] = 0ull;

    for (int kt = 0; kt < 16; kt++) {
        const int k0 = kt * 32;
#pragma unroll
        for (int m = 0; m < 8; m++) {
            int f4 = tid + m * 128;
            int g = f4 >> 3, kq = f4 & 7;
            float4 v = *(const float4*)&W_ih[(size_t)(g0 + g) * D_ + k0 + kq * 4];
            *(float4*)&ws[g * 36 + kq * 4] = v;
        }
#pragma unroll
        for (int m = 0; m < 2; m++) {
            int f4 = tid + m * 128;
            int b = f4 >> 3, kq = f4 & 7;
            float4 v = *(const float4*)&input[((size_t)b * T_ + t) * D_ + k0 + kq * 4];
            xs[(kq * 4 + 0) * XS_ + b] = v.x;
            xs[(kq * 4 + 1) * XS_ + b] = v.y;
            xs[(kq * 4 + 2) * XS_ + b] = v.z;
            xs[(kq * 4 + 3) * XS_ + b] = v.w;
        }
        __syncthreads();

#pragma unroll
        for (int k4 = 0; k4 < 8; k4++) {
            float4 wv[8];
#pragma unroll
            for (int i = 0; i < 8; i++)
                wv[i] = *(const float4*)&ws[(gg + 16 * i) * 36 + k4 * 4];
#pragma unroll
            for (int kk = 0; kk < 4; kk++) {
                const float* xrow = &xs[(k4 * 4 + kk) * XS_ + bg * 4];
                unsigned long long x2a = *(const unsigned long long*)(xrow);
                unsigned long long x2b = *(const unsigned long long*)(xrow + 2);
#pragma unroll
                for (int i = 0; i < 8; i++) {
                    float w = (kk == 0) ? wv[i].x : (kk == 1) ? wv[i].y
                             : (kk == 2) ? wv[i].z : wv[i].w;
                    unsigned long long w2 = pack2(w, w);
                    fma2(acc2[i * 2 + 0], w2, x2a);
                    fma2(acc2[i * 2 + 1], w2, x2b);
                }
            }
        }
        __syncthreads();
    }

#pragma unroll
    for (int i = 0; i < 8; i++) {
        int g = g0 + gg + 16 * i;
        float bias = b_ih[g] + b_hh[g];
        float4 o; float lo, hi;
        unpack2(acc2[i * 2 + 0], lo, hi); o.x = lo + bias; o.y = hi + bias;
        unpack2(acc2[i * 2 + 1], lo, hi); o.z = lo + bias; o.w = hi + bias;
        *(float4*)&g_xproj[((size_t)t * G4_ + g) * B_ + bg * 4] = o;
    }
}

// ---------------- Phase 2: recurrence, quarter-staged dataflow -----------------
// 128 blocks = 32 jg x 4 bg, 512 threads. Warp w = local j; lane k-slice
// k = lane + 32*(q*4+cc). h split into 4 k-quarters; quarter q produced by
// blocks jg = 8q..8q+7 (sharing bg). Staging threads (tid<256) acquire-poll
// their quarter's producer flag and cp.async the 4KB quarter into a
// double-buffered smem slot; GEMM(q) overlaps stage(q+1).
extern "C" __global__ void __launch_bounds__(512, 1) lstm_rec_kernel(
    const float* __restrict__ h0,
    const float* __restrict__ c0,
    const float* __restrict__ W_hh,
    float* __restrict__ out)
{
    __shared__ float bufs[2][8 * HQS];         // [slot][bl][kk]

    const int tid  = threadIdx.x;
    const int bid  = blockIdx.x;
    const int jg   = bid >> 2;
    const int bg   = bid & 3;
    const int w    = tid >> 5;                 // local j
    const int lane = tid & 31;
    const int j    = jg * 16 + w;

    // ---- W_hh rows (4 gates of row j) into registers ----
    float wreg[64];
#pragma unroll
    for (int i = 0; i < 4; i++) {
        const float* wrow = &W_hh[(size_t)(i * H_ + j) * H_];
#pragma unroll
        for (int kc = 0; kc < 16; kc++)
            wreg[i * 16 + kc] = wrow[lane + 32 * kc];
    }

    const int b_mine = bg * 8 + (lane & 7);
    float creg = c0[(size_t)b_mine * H_ + j];

    const unsigned epoch = *((volatile unsigned*)&g_epoch);
    const unsigned base  = epoch * 4096u;

    const float* xp_base =
        &g_xproj[(size_t)((lane >> 3) * H_ + j) * B_ + b_mine];
    unsigned* my_flag = &g_flags[bid * 64];

    // staging role (tid < 256): row bl, 16B chunk kk..kk+3 of each quarter
    const int st_bl = tid >> 5;                // 0..7 (valid when tid<256)
    const int st_kk = (tid * 4) & 127;         // 16B-aligned chunk start
    const int st_jgl = st_kk >> 4;             // producer jg offset within quarter

    __syncthreads();

    for (int t = 0; t < T_; t++) {
        const float* hprev = (t == 0) ? h0 : g_h[(t - 1) & 1];
        const unsigned tgt = base + (unsigned)t;
        float xp = __ldcg(xp_base + (size_t)t * (G4_ * B_));

        // ---- prologue: stage quarter 0 into slot 0 ----
        if (tid < 256) {
            if (t > 0) {
                const unsigned* f = &g_flags[(st_jgl * 4 + bg) * 64];
                unsigned v = ld_acq(f);
                while (v < tgt) { __nanosleep(64); v = ld_acq(f); }
            }
            cp_async16(smem_u32(&bufs[0][st_bl * HQS + st_kk]),
                       hprev + (size_t)(8 * bg + st_bl) * H_ + st_kk);
        }
        cp_commit();
        cp_wait0();
        __syncthreads();

        unsigned long long acc2[16];
#pragma unroll
        for (int q16 = 0; q16 < 16; q16++) acc2[q16] = 0ull;

#pragma unroll
        for (int q = 0; q < 4; q++) {
            // stage quarter q+1 into the other slot (overlaps GEMM(q))
            if (q < 3) {
                if (tid < 256) {
                    const int qs = q + 1;
                    if (t > 0) {
                        const unsigned* f =
                            &g_flags[((8 * qs + st_jgl) * 4 + bg) * 64];
                        unsigned v = ld_acq(f);
                        while (v < tgt) { __nanosleep(64); v = ld_acq(f); }
                    }
                    cp_async16(smem_u32(&bufs[qs & 1][st_bl * HQS + st_kk]),
                               hprev + (size_t)(8 * bg + st_bl) * H_
                                     + 128 * qs + st_kk);
                }
                cp_commit();
            }

            // ---- GEMM on quarter q from bufs[q&1] ----
            const float* buf = bufs[q & 1];
#pragma unroll
            for (int cc = 0; cc < 4; cc++) {
                const int kc = q * 4 + cc;
                const int kk = lane + 32 * cc;
                float hb[8];
#pragma unroll
                for (int bl = 0; bl < 8; bl++) hb[bl] = buf[bl * HQS + kk];
                unsigned long long h2[4];
#pragma unroll
                for (int jp = 0; jp < 4; jp++)
                    h2[jp] = pack2(hb[2 * jp], hb[2 * jp + 1]);
#pragma unroll
                for (int i = 0; i < 4; i++) {
                    const float wv = wreg[i * 16 + kc];
                    unsigned long long w2 = pack2(wv, wv);
#pragma unroll
                    for (int jp = 0; jp < 4; jp++)
                        fma2(acc2[i * 4 + jp], w2, h2[jp]);
                }
            }
            cp_wait0();
            __syncthreads();
        }

        // ---- butterfly reduce, stage-16 folded into unpack ----
        float v16[16];
#pragma unroll
        for (int i = 0; i < 2; i++)
#pragma unroll
            for (int jp = 0; jp < 4; jp++) {
                float alo, ahi, blo, bhi;
                unpack2(acc2[i * 4 + jp],       alo, ahi);
                unpack2(acc2[(i + 2) * 4 + jp], blo, bhi);
                int s0 = i * 8 + 2 * jp;
                float ta = __shfl_xor_sync(0xffffffffu, alo, 16);
                float tb = __shfl_xor_sync(0xffffffffu, blo, 16);
                v16[s0] = (lane & 16) ? (blo + tb) : (alo + ta);
                ta = __shfl_xor_sync(0xffffffffu, ahi, 16);
                tb = __shfl_xor_sync(0xffffffffu, bhi, 16);
                v16[s0 + 1] = (lane & 16) ? (bhi + tb) : (ahi + ta);
            }
#pragma unroll
        for (int s = 0; s < 8; s++) {
            float ta = __shfl_xor_sync(0xffffffffu, v16[s], 8);
            float tb = __shfl_xor_sync(0xffffffffu, v16[s + 8], 8);
            v16[s] = (lane & 8) ? (v16[s + 8] + tb) : (v16[s] + ta);
        }
#pragma unroll
        for (int s = 0; s < 4; s++) {
            float ta = __shfl_xor_sync(0xffffffffu, v16[s], 4);
            float tb = __shfl_xor_sync(0xffffffffu, v16[s + 4], 4);
            v16[s] = (lane & 4) ? (v16[s + 4] + tb) : (v16[s] + ta);
        }
#pragma unroll
        for (int s = 0; s < 2; s++) {
            float ta = __shfl_xor_sync(0xffffffffu, v16[s], 2);
            float tb = __shfl_xor_sync(0xffffffffu, v16[s + 2], 2);
            v16[s] = (lane & 2) ? (v16[s + 2] + tb) : (v16[s] + ta);
        }
        {
            float ta = __shfl_xor_sync(0xffffffffu, v16[0], 1);
            float tb = __shfl_xor_sync(0xffffffffu, v16[1], 1);
            v16[0] = (lane & 1) ? (v16[1] + tb) : (v16[0] + ta);
        }
        float pre = v16[0] + xp;   // lane L: gate L>>3, batch bg*8+(L&7)

        // ---- in-warp activations ----
        float xf = __shfl_down_sync(0xffffffffu, pre, 8);
        float xg = __shfl_down_sync(0xffffffffu, pre, 16);
        float xo = __shfl_down_sync(0xffffffffu, pre, 24);
        float iv = sigmoid_fast(pre);
        float fv = sigmoid_fast(xf);
        float gv = tanh_approx(xg);
        float ov = sigmoid_fast(xo);
        float cn = fv * creg + iv * gv;
        float hn = ov * tanh_approx(cn);
        if (lane < 8) {
            creg = cn;
            __stcg(&g_h[t & 1][(size_t)b_mine * H_ + j], hn);
            if (t == T_ - 1) {
                out[(size_t)b_mine * H_ + j]           = hn;
                out[(size_t)B_ * H_ + b_mine * H_ + j] = cn;
            }
        }
        __syncthreads();   // all warps' h stores precede the release
        if (tid == 0) st_rel(my_flag, base + (unsigned)t + 1u);
        // no trailing barrier: next step's per-quarter polls gate progress
    }
}

// ---------------- launch ------------------------------------------------------
extern "C" void kernel_launch(void* const* d_in, const int* in_sizes, int n_in,
                              void* d_out, int out_size)
{
    const float* input = (const float*)d_in[0];
    const float* h0    = (const float*)d_in[1];
    const float* c0    = (const float*)d_in[2];
    const float* W_ih  = (const float*)d_in[3];
    const float* W_hh  = (const float*)d_in[4];
    const float* b_ih  = (const float*)d_in[5];
    const float* b_hh  = (const float*)d_in[6];
    float* out = (float*)d_out;

    dim3 grid1(T_, 16);
    lstm_xproj_kernel<<<grid1, 128>>>(input, W_ih, b_ih, b_hh);

    lstm_epoch_kernel<<<1, 1>>>();

    lstm_rec_kernel<<<NBLK, 512>>>(h0, c0, W_hh, out);
}

// round 14
// speedup vs baseline: 1.1243x; 1.1243x over previous
#include <cuda_runtime.h>
#include <math.h>
#include <stdint.h>

#define B_   32
#define T_   2048
#define D_   512
#define H_   512
#define G4_  2048
#define NBLK 128
#define XS_  34
#define HSK  516        // hsm row stride (floats); bank = lane + 4*bl, conflict-free

// ---------------- device scratch ----------------------------------------------
__device__ float g_xproj[(size_t)T_ * G4_ * B_];   // [t][g][b]
__device__ __align__(16) float g_h[2][B_ * H_];    // [b][j]  double-buffered
__device__ unsigned g_epoch;
__device__ unsigned g_flags[NBLK * 64];            // one flag per 256B line

// ---------------- helpers -------------------------------------------------------
__device__ __forceinline__ unsigned long long pack2(float lo, float hi) {
    unsigned long long r;
    asm("mov.b64 %0, {%1, %2};" : "=l"(r) : "f"(lo), "f"(hi));
    return r;
}
__device__ __forceinline__ void fma2(unsigned long long& d,
                                     unsigned long long a, unsigned long long b) {
    asm("fma.rn.f32x2 %0, %1, %2, %0;" : "+l"(d) : "l"(a), "l"(b));
}
__device__ __forceinline__ void unpack2(unsigned long long v, float& lo, float& hi) {
    asm("mov.b64 {%0, %1}, %2;" : "=f"(lo), "=f"(hi) : "l"(v));
}
__device__ __forceinline__ unsigned ld_acq(const unsigned* p) {
    unsigned v;
    asm volatile("ld.acquire.gpu.u32 %0, [%1];" : "=r"(v) : "l"(p) : "memory");
    return v;
}
__device__ __forceinline__ void st_rel(unsigned* p, unsigned v) {
    asm volatile("st.release.gpu.u32 [%0], %1;" :: "l"(p), "r"(v) : "memory");
}
__device__ __forceinline__ float tanh_approx(float x) {
    float y;
    asm("tanh.approx.f32 %0, %1;" : "=f"(y) : "f"(x));
    return y;
}
__device__ __forceinline__ float sigmoid_fast(float x) {
    return fmaf(tanh_approx(0.5f * x), 0.5f, 0.5f);
}

__global__ void lstm_epoch_kernel() {
    if (threadIdx.x == 0) g_epoch = g_epoch + 1u;
}

// ---------------- Phase 1: x_proj (retiled 4g x 8b) ----------------------------
// grid (T_,16), 128 threads. Thread (gg=tid>>2, bg=tid&3): rows g = gg+32i (i<4),
// batches b = bg*8..+7 (4 f32x2 pairs). Halves ws crossbar reads vs 8g x 4b.
__global__ void __launch_bounds__(128, 4) lstm_xproj_kernel(
    const float* __restrict__ input,
    const float* __restrict__ W_ih,
    const float* __restrict__ b_ih,
    const float* __restrict__ b_hh)
{
    __shared__ float ws[128 * 36];
    __shared__ float xs[32 * XS_];

    const int t   = blockIdx.x;
    const int g0  = blockIdx.y * 128;
    const int tid = threadIdx.x;
    const int gg  = tid >> 2;        // 0..31
    const int bg  = tid & 3;         // 0..3 -> b = bg*8..+7

    unsigned long long acc2[16];     // [i][p]  i<4 rows, p<4 b-pairs
#pragma unroll
    for (int v = 0; v < 16; v++) acc2[v] = 0ull;

    for (int kt = 0; kt < 16; kt++) {
        const int k0 = kt * 32;
#pragma unroll
        for (int m = 0; m < 8; m++) {                  // W tile: 128g x 32k
            int f4 = tid + m * 128;
            int g = f4 >> 3, kq = f4 & 7;
            float4 v = *(const float4*)&W_ih[(size_t)(g0 + g) * D_ + k0 + kq * 4];
            *(float4*)&ws[g * 36 + kq * 4] = v;
        }
#pragma unroll
        for (int m = 0; m < 2; m++) {                  // x tile: 32b x 32k
            int f4 = tid + m * 128;
            int b = f4 >> 3, kq = f4 & 7;
            float4 v = *(const float4*)&input[((size_t)b * T_ + t) * D_ + k0 + kq * 4];
            xs[(kq * 4 + 0) * XS_ + b] = v.x;
            xs[(kq * 4 + 1) * XS_ + b] = v.y;
            xs[(kq * 4 + 2) * XS_ + b] = v.z;
            xs[(kq * 4 + 3) * XS_ + b] = v.w;
        }
        __syncthreads();

#pragma unroll
        for (int k4 = 0; k4 < 8; k4++) {
            float4 wv[4];
#pragma unroll
            for (int i = 0; i < 4; i++)
                wv[i] = *(const float4*)&ws[(gg + 32 * i) * 36 + k4 * 4];
#pragma unroll
            for (int kk = 0; kk < 4; kk++) {
                const float* xrow = &xs[(k4 * 4 + kk) * XS_ + bg * 8];
                unsigned long long x2[4];
#pragma unroll
                for (int p = 0; p < 4; p++)
                    x2[p] = *(const unsigned long long*)(xrow + 2 * p);
#pragma unroll
                for (int i = 0; i < 4; i++) {
                    float w = (kk == 0) ? wv[i].x : (kk == 1) ? wv[i].y
                             : (kk == 2) ? wv[i].z : wv[i].w;
                    unsigned long long w2 = pack2(w, w);
#pragma unroll
                    for (int p = 0; p < 4; p++) fma2(acc2[i * 4 + p], w2, x2[p]);
                }
            }
        }
        __syncthreads();
    }

#pragma unroll
    for (int i = 0; i < 4; i++) {
        int g = g0 + gg + 32 * i;
        float bias = b_ih[g] + b_hh[g];
        float* op = &g_xproj[((size_t)t * G4_ + g) * B_ + bg * 8];
        float4 o; float lo, hi;
        unpack2(acc2[i * 4 + 0], lo, hi); o.x = lo + bias; o.y = hi + bias;
        unpack2(acc2[i * 4 + 1], lo, hi); o.z = lo + bias; o.w = hi + bias;
        *(float4*)op = o;
        unpack2(acc2[i * 4 + 2], lo, hi); o.x = lo + bias; o.y = hi + bias;
        unpack2(acc2[i * 4 + 3], lo, hi); o.z = lo + bias; o.w = hi + bias;
        *(float4*)(op + 4) = o;
    }
}

// ---------------- Phase 2: persistent recurrence (R6 base, gate-pair GEMM) -----
// 128 blocks = 32 jg x 4 bg, 512 threads. Warp w = local j; lane = k-slice
// (k = lane+32kc). W pre-packed as gate-pairs (loop-invariant f32x2 operands):
// acc2[gp*8+bl] accumulates (gate 2gp, gate 2gp+1) for batch bl.
extern "C" __global__ void __launch_bounds__(512, 1) lstm_rec_kernel(
    const float* __restrict__ h0,
    const float* __restrict__ c0,
    const float* __restrict__ W_hh,
    float* __restrict__ out)
{
    extern __shared__ float smem[];
    float* hsm = smem;                         // [8][HSK]  ([b_local][k])

    const int tid  = threadIdx.x;
    const int bid  = blockIdx.x;
    const int jg   = bid >> 2;
    const int bg   = bid & 3;
    const int w    = tid >> 5;                 // local j
    const int lane = tid & 31;
    const int j    = jg * 16 + w;

    // ---- W_hh gate-pair packs (loop-invariant): w2pk[gp*16+kc] ----
    unsigned long long w2pk[32];
#pragma unroll
    for (int gp = 0; gp < 2; gp++) {
        const float* r0 = &W_hh[(size_t)((2 * gp)     * H_ + j) * H_];
        const float* r1 = &W_hh[(size_t)((2 * gp + 1) * H_ + j) * H_];
#pragma unroll
        for (int kc = 0; kc < 16; kc++) {
            int k = lane + 32 * kc;
            w2pk[gp * 16 + kc] = pack2(r0[k], r1[k]);
        }
    }

    const int b_mine = bg * 8 + (lane & 7);
    float creg = c0[(size_t)b_mine * H_ + j];

    const unsigned epoch = *((volatile unsigned*)&g_epoch);
    const unsigned base  = epoch * 4096u;

    const float* xp_base =
        &g_xproj[(size_t)((lane >> 3) * H_ + j) * B_ + b_mine];
    unsigned* my_flag = &g_flags[bid * 64];
    const unsigned* my_peer_flag = &g_flags[((lane * 4) + bg) * 64];

    __syncthreads();

    for (int t = 0; t < T_; t++) {
        // ---- stage h rows bg*8..+7 into hsm[b_local][k] ----
        const float* hsrc =
            ((t == 0) ? h0 : g_h[(t - 1) & 1]) + (size_t)(bg * 8) * H_;
#pragma unroll
        for (int m = 0; m < 2; m++) {
            int f4 = tid + m * 512;
            int bl = f4 >> 7, kq = f4 & 127;
            float4 v = __ldcg((const float4*)(hsrc + bl * H_) + kq);
            *(float4*)&hsm[bl * HSK + kq * 4] = v;
        }
        float xp = __ldcg(xp_base + (size_t)t * (G4_ * B_));
        __syncthreads();

        // ---- GEMM: gate-pair f32x2, W packs pre-made ----
        unsigned long long acc2[16];
#pragma unroll
        for (int q = 0; q < 16; q++) acc2[q] = 0ull;

#pragma unroll
        for (int kc = 0; kc < 16; kc++) {
            const int k = lane + 32 * kc;
            unsigned long long h2[8];
#pragma unroll
            for (int bl = 0; bl < 8; bl++) {
                float hv = hsm[bl * HSK + k];
                h2[bl] = pack2(hv, hv);
            }
#pragma unroll
            for (int gp = 0; gp < 2; gp++) {
                const unsigned long long w2 = w2pk[gp * 16 + kc];
#pragma unroll
                for (int bl = 0; bl < 8; bl++)
                    fma2(acc2[gp * 8 + bl], w2, h2[bl]);
            }
        }

        // ---- butterfly reduce; stage-16 fold sources the gate-pair layout ----
        // v[s] (s = gate*8+b): gate0=acc2[b].lo gate1=acc2[b].hi
        //                      gate2=acc2[8+b].lo gate3=acc2[8+b].hi
        float v16[16];
#pragma unroll
        for (int b = 0; b < 8; b++) {
            float alo, ahi, blo, bhi;
            unpack2(acc2[b],     alo, ahi);    // gates 0,1
            unpack2(acc2[8 + b], blo, bhi);    // gates 2,3
            float ta = __shfl_xor_sync(0xffffffffu, alo, 16);
            float tb = __shfl_xor_sync(0xffffffffu, blo, 16);
            v16[b] = (lane & 16) ? (blo + tb) : (alo + ta);
            ta = __shfl_xor_sync(0xffffffffu, ahi, 16);
            tb = __shfl_xor_sync(0xffffffffu, bhi, 16);
            v16[8 + b] = (lane & 16) ? (bhi + tb) : (ahi + ta);
        }
#pragma unroll
        for (int s = 0; s < 8; s++) {
            float ta = __shfl_xor_sync(0xffffffffu, v16[s], 8);
            float tb = __shfl_xor_sync(0xffffffffu, v16[s + 8], 8);
            v16[s] = (lane & 8) ? (v16[s + 8] + tb) : (v16[s] + ta);
        }
#pragma unroll
        for (int s = 0; s < 4; s++) {
            float ta = __shfl_xor_sync(0xffffffffu, v16[s], 4);
            float tb = __shfl_xor_sync(0xffffffffu, v16[s + 4], 4);
            v16[s] = (lane & 4) ? (v16[s + 4] + tb) : (v16[s] + ta);
        }
#pragma unroll
        for (int s = 0; s < 2; s++) {
            float ta = __shfl_xor_sync(0xffffffffu, v16[s], 2);
            float tb = __shfl_xor_sync(0xffffffffu, v16[s + 2], 2);
            v16[s] = (lane & 2) ? (v16[s + 2] + tb) : (v16[s] + ta);
        }
        {
            float ta = __shfl_xor_sync(0xffffffffu, v16[0], 1);
            float tb = __shfl_xor_sync(0xffffffffu, v16[1], 1);
            v16[0] = (lane & 1) ? (v16[1] + tb) : (v16[0] + ta);
        }
        float pre = v16[0] + xp;   // lane L: gate L>>3, batch bg*8+(L&7)

        // ---- in-warp activations ----
        float xf = __shfl_down_sync(0xffffffffu, pre, 8);
        float xg = __shfl_down_sync(0xffffffffu, pre, 16);
        float xo = __shfl_down_sync(0xffffffffu, pre, 24);
        float iv = sigmoid_fast(pre);
        float fv = sigmoid_fast(xf);
        float gv = tanh_approx(xg);
        float ov = sigmoid_fast(xo);
        float cn = fv * creg + iv * gv;
        float hn = ov * tanh_approx(cn);
        if (lane < 8) {
            creg = cn;
            __stcg(&g_h[t & 1][(size_t)b_mine * H_ + j], hn);
            if (t == T_ - 1) {
                out[(size_t)b_mine * H_ + j]           = hn;
                out[(size_t)B_ * H_ + b_mine * H_ + j] = cn;
            }
        }
        __syncthreads();   // all warps' h stores precede the release

        // ---- chain barrier: 32 peers sharing bg, padded flags ----
        const unsigned target = base + (unsigned)t + 1u;
        if (tid == 0) st_rel(my_flag, target);
        if (tid < 32) {
            while (ld_acq(my_peer_flag) < target) { }
        }
        __syncthreads();
    }
}

// ---------------- launch ------------------------------------------------------
extern "C" void kernel_launch(void* const* d_in, const int* in_sizes, int n_in,
                              void* d_out, int out_size)
{
    const float* input = (const float*)d_in[0];
    const float* h0    = (const float*)d_in[1];
    const float* c0    = (const float*)d_in[2];
    const float* W_ih  = (const float*)d_in[3];
    const float* W_hh  = (const float*)d_in[4];
    const float* b_ih  = (const float*)d_in[5];
    const float* b_hh  = (const float*)d_in[6];
    float* out = (float*)d_out;

    dim3 grid1(T_, 16);
    lstm_xproj_kernel<<<grid1, 128>>>(input, W_ih, b_ih, b_hh);

    lstm_epoch_kernel<<<1, 1>>>();

    const int smem_bytes = (8 * HSK) * sizeof(float);
    cudaFuncSetAttribute(lstm_rec_kernel,
                         cudaFuncAttributeMaxDynamicSharedMemorySize, smem_bytes);
    lstm_rec_kernel<<<NBLK, 512, smem_bytes>>>(h0, c0, W_hh, out);
}

// round 15
// speedup vs baseline: 1.1369x; 1.0113x over previous
#include <cuda_runtime.h>
#include <math.h>
#include <stdint.h>

#define B_   32
#define T_   2048
#define D_   512
#define H_   512
#define G4_  2048
#define NBLK 128
#define XS_  34
#define HSK  516        // hsm row stride (floats)

// ---------------- device scratch ----------------------------------------------
__device__ float g_xproj[(size_t)T_ * G4_ * B_];   // [t][g][b]
__device__ __align__(16) float g_h[2][H_ * B_];    // [j][b]  double-buffered
__device__ unsigned g_epoch;
__device__ unsigned g_flags[NBLK * 64];            // one flag per 256B line

// ---------------- helpers -------------------------------------------------------
__device__ __forceinline__ unsigned long long pack2(float lo, float hi) {
    unsigned long long r;
    asm("mov.b64 %0, {%1, %2};" : "=l"(r) : "f"(lo), "f"(hi));
    return r;
}
__device__ __forceinline__ void fma2(unsigned long long& d,
                                     unsigned long long a, unsigned long long b) {
    asm("fma.rn.f32x2 %0, %1, %2, %0;" : "+l"(d) : "l"(a), "l"(b));
}
__device__ __forceinline__ void unpack2(unsigned long long v, float& lo, float& hi) {
    asm("mov.b64 {%0, %1}, %2;" : "=f"(lo), "=f"(hi) : "l"(v));
}
__device__ __forceinline__ unsigned ld_acq(const unsigned* p) {
    unsigned v;
    asm volatile("ld.acquire.gpu.u32 %0, [%1];" : "=r"(v) : "l"(p) : "memory");
    return v;
}
__device__ __forceinline__ void st_rel(unsigned* p, unsigned v) {
    asm volatile("st.release.gpu.u32 [%0], %1;" :: "l"(p), "r"(v) : "memory");
}
__device__ __forceinline__ float tanh_approx(float x) {
    float y;
    asm("tanh.approx.f32 %0, %1;" : "=f"(y) : "f"(x));
    return y;
}
__device__ __forceinline__ float sigmoid_fast(float x) {
    return fmaf(tanh_approx(0.5f * x), 0.5f, 0.5f);
}

__global__ void lstm_epoch_kernel() {
    if (threadIdx.x == 0) g_epoch = g_epoch + 1u;
}

// ---------------- Phase 1: x_proj (REVERTED to measured-best 8g x 4b) ----------
__global__ void __launch_bounds__(128, 4) lstm_xproj_kernel(
    const float* __restrict__ input,
    const float* __restrict__ W_ih,
    const float* __restrict__ b_ih,
    const float* __restrict__ b_hh)
{
    __shared__ float ws[128 * 36];
    __shared__ float xs[32 * XS_];

    const int t   = blockIdx.x;
    const int g0  = blockIdx.y * 128;
    const int tid = threadIdx.x;
    const int gg  = tid >> 3;
    const int bg  = tid & 7;

    unsigned long long acc2[16];
#pragma unroll
    for (int v = 0; v < 16; v++) acc2[v] = 0ull;

    for (int kt = 0; kt < 16; kt++) {
        const int k0 = kt * 32;
#pragma unroll
        for (int m = 0; m < 8; m++) {
            int f4 = tid + m * 128;
            int g = f4 >> 3, kq = f4 & 7;
            float4 v = *(const float4*)&W_ih[(size_t)(g0 + g) * D_ + k0 + kq * 4];
            *(float4*)&ws[g * 36 + kq * 4] = v;
        }
#pragma unroll
        for (int m = 0; m < 2; m++) {
            int f4 = tid + m * 128;
            int b = f4 >> 3, kq = f4 & 7;
            float4 v = *(const float4*)&input[((size_t)b * T_ + t) * D_ + k0 + kq * 4];
            xs[(kq * 4 + 0) * XS_ + b] = v.x;
            xs[(kq * 4 + 1) * XS_ + b] = v.y;
            xs[(kq * 4 + 2) * XS_ + b] = v.z;
            xs[(kq * 4 + 3) * XS_ + b] = v.w;
        }
        __syncthreads();

#pragma unroll
        for (int k4 = 0; k4 < 8; k4++) {
            float4 wv[8];
#pragma unroll
            for (int i = 0; i < 8; i++)
                wv[i] = *(const float4*)&ws[(gg + 16 * i) * 36 + k4 * 4];
#pragma unroll
            for (int kk = 0; kk < 4; kk++) {
                const float* xrow = &xs[(k4 * 4 + kk) * XS_ + bg * 4];
                unsigned long long x2a = *(const unsigned long long*)(xrow);
                unsigned long long x2b = *(const unsigned long long*)(xrow + 2);
#pragma unroll
                for (int i = 0; i < 8; i++) {
                    float w = (kk == 0) ? wv[i].x : (kk == 1) ? wv[i].y
                             : (kk == 2) ? wv[i].z : wv[i].w;
                    unsigned long long w2 = pack2(w, w);
                    fma2(acc2[i * 2 + 0], w2, x2a);
                    fma2(acc2[i * 2 + 1], w2, x2b);
                }
            }
        }
        __syncthreads();
    }

#pragma unroll
    for (int i = 0; i < 8; i++) {
        int g = g0 + gg + 16 * i;
        float bias = b_ih[g] + b_hh[g];
        float4 o; float lo, hi;
        unpack2(acc2[i * 2 + 0], lo, hi); o.x = lo + bias; o.y = hi + bias;
        unpack2(acc2[i * 2 + 1], lo, hi); o.z = lo + bias; o.w = hi + bias;
        *(float4*)&g_xproj[((size_t)t * G4_ + g) * B_ + bg * 4] = o;
    }
}

// ---------------- Phase 2: recurrence (gate-pair GEMM kept; h in [j][b]) -------
// 128 blocks = 32 jg x 4 bg, 512 threads. Producer h-stores now COALESCED
// (warp lanes 0..7 -> 32B contiguous in [j][b]); consumer stages via
// sector-aligned ld.v2 + conflict-free smem transpose into hsm[bl][k].
extern "C" __global__ void __launch_bounds__(512, 1) lstm_rec_kernel(
    const float* __restrict__ h0,
    const float* __restrict__ c0,
    const float* __restrict__ W_hh,
    float* __restrict__ out)
{
    extern __shared__ float smem[];
    float* hsm = smem;                         // [8][HSK]  ([b_local][k])

    const int tid  = threadIdx.x;
    const int bid  = blockIdx.x;
    const int jg   = bid >> 2;
    const int bg   = bid & 3;
    const int w    = tid >> 5;                 // local j
    const int lane = tid & 31;
    const int j    = jg * 16 + w;

    // ---- W_hh gate-pair packs (loop-invariant): w2pk[gp*16+kc] ----
    unsigned long long w2pk[32];
#pragma unroll
    for (int gp = 0; gp < 2; gp++) {
        const float* r0 = &W_hh[(size_t)((2 * gp)     * H_ + j) * H_];
        const float* r1 = &W_hh[(size_t)((2 * gp + 1) * H_ + j) * H_];
#pragma unroll
        for (int kc = 0; kc < 16; kc++) {
            int k = lane + 32 * kc;
            w2pk[gp * 16 + kc] = pack2(r0[k], r1[k]);
        }
    }

    const int b_mine = bg * 8 + (lane & 7);
    float creg = c0[(size_t)b_mine * H_ + j];

    const unsigned epoch = *((volatile unsigned*)&g_epoch);
    const unsigned base  = epoch * 4096u;

    const float* xp_base =
        &g_xproj[(size_t)((lane >> 3) * H_ + j) * B_ + b_mine];
    unsigned* my_flag = &g_flags[bid * 64];
    const unsigned* my_peer_flag = &g_flags[((lane * 4) + bg) * 64];

    __syncthreads();

    for (int t = 0; t < T_; t++) {
        // ---- stage h into hsm[b_local][k] ----
        if (t == 0) {
            // h0 is [b][j]
#pragma unroll
            for (int m = 0; m < 4; m++) {
                int idx = m * 512 + tid;       // 0..2047
                int k = idx >> 2, p = idx & 3;
                int b0 = bg * 8 + 2 * p;
                hsm[(2 * p) * HSK + k]     = h0[(size_t)b0 * H_ + k];
                hsm[(2 * p + 1) * HSK + k] = h0[(size_t)(b0 + 1) * H_ + k];
            }
        } else {
            const float* hsrc = g_h[(t - 1) & 1];      // [j][b] flat k*32+b
#pragma unroll
            for (int m = 0; m < 4; m++) {
                int idx = m * 512 + tid;
                int k = idx >> 2, p = idx & 3;
                float2 v = __ldcg((const float2*)&hsrc[k * B_ + bg * 8 + 2 * p]);
                hsm[(2 * p) * HSK + k]     = v.x;
                hsm[(2 * p + 1) * HSK + k] = v.y;
            }
        }
        float xp = __ldcg(xp_base + (size_t)t * (G4_ * B_));
        __syncthreads();

        // ---- GEMM: gate-pair f32x2, W packs pre-made ----
        unsigned long long acc2[16];
#pragma unroll
        for (int q = 0; q < 16; q++) acc2[q] = 0ull;

#pragma unroll
        for (int kc = 0; kc < 16; kc++) {
            const int k = lane + 32 * kc;
            unsigned long long h2[8];
#pragma unroll
            for (int bl = 0; bl < 8; bl++) {
                float hv = hsm[bl * HSK + k];
                h2[bl] = pack2(hv, hv);
            }
#pragma unroll
            for (int gp = 0; gp < 2; gp++) {
                const unsigned long long w2 = w2pk[gp * 16 + kc];
#pragma unroll
                for (int bl = 0; bl < 8; bl++)
                    fma2(acc2[gp * 8 + bl], w2, h2[bl]);
            }
        }

        // ---- butterfly reduce; stage-16 fold sources gate-pair layout ----
        float v16[16];
#pragma unroll
        for (int b = 0; b < 8; b++) {
            float alo, ahi, blo, bhi;
            unpack2(acc2[b],     alo, ahi);    // gates 0,1
            unpack2(acc2[8 + b], blo, bhi);    // gates 2,3
            float ta = __shfl_xor_sync(0xffffffffu, alo, 16);
            float tb = __shfl_xor_sync(0xffffffffu, blo, 16);
            v16[b] = (lane & 16) ? (blo + tb) : (alo + ta);
            ta = __shfl_xor_sync(0xffffffffu, ahi, 16);
            tb = __shfl_xor_sync(0xffffffffu, bhi, 16);
            v16[8 + b] = (lane & 16) ? (bhi + tb) : (ahi + ta);
        }
#pragma unroll
        for (int s = 0; s < 8; s++) {
            float ta = __shfl_xor_sync(0xffffffffu, v16[s], 8);
            float tb = __shfl_xor_sync(0xffffffffu, v16[s + 8], 8);
            v16[s] = (lane & 8) ? (v16[s + 8] + tb) : (v16[s] + ta);
        }
#pragma unroll
        for (int s = 0; s < 4; s++) {
            float ta = __shfl_xor_sync(0xffffffffu, v16[s], 4);
            float tb = __shfl_xor_sync(0xffffffffu, v16[s + 4], 4);
            v16[s] = (lane & 4) ? (v16[s + 4] + tb) : (v16[s] + ta);
        }
#pragma unroll
        for (int s = 0; s < 2; s++) {
            float ta = __shfl_xor_sync(0xffffffffu, v16[s], 2);
            float tb = __shfl_xor_sync(0xffffffffu, v16[s + 2], 2);
            v16[s] = (lane & 2) ? (v16[s + 2] + tb) : (v16[s] + ta);
        }
        {
            float ta = __shfl_xor_sync(0xffffffffu, v16[0], 1);
            float tb = __shfl_xor_sync(0xffffffffu, v16[1], 1);
            v16[0] = (lane & 1) ? (v16[1] + tb) : (v16[0] + ta);
        }
        float pre = v16[0] + xp;   // lane L: gate L>>3, batch bg*8+(L&7)

        // ---- in-warp activations ----
        float xf = __shfl_down_sync(0xffffffffu, pre, 8);
        float xg = __shfl_down_sync(0xffffffffu, pre, 16);
        float xo = __shfl_down_sync(0xffffffffu, pre, 24);
        float iv = sigmoid_fast(pre);
        float fv = sigmoid_fast(xf);
        float gv = tanh_approx(xg);
        float ov = sigmoid_fast(xo);
        float cn = fv * creg + iv * gv;
        float hn = ov * tanh_approx(cn);
        if (lane < 8) {
            creg = cn;
            // [j][b]: warp lanes 0..7 -> 32B contiguous, coalesced
            __stcg(&g_h[t & 1][(size_t)j * B_ + b_mine], hn);
            if (t == T_ - 1) {
                out[(size_t)b_mine * H_ + j]           = hn;   // [b][j]
                out[(size_t)B_ * H_ + b_mine * H_ + j] = cn;
            }
        }
        __syncthreads();   // all warps' h stores precede the release

        // ---- chain barrier: 32 peers sharing bg, padded flags ----
        const unsigned target = base + (unsigned)t + 1u;
        if (tid == 0) st_rel(my_flag, target);
        if (tid < 32) {
            while (ld_acq(my_peer_flag) < target) { }
        }
        __syncthreads();
    }
}

// ---------------- launch ------------------------------------------------------
extern "C" void kernel_launch(void* const* d_in, const int* in_sizes, int n_in,
                              void* d_out, int out_size)
{
    const float* input = (const float*)d_in[0];
    const float* h0    = (const float*)d_in[1];
    const float* c0    = (const float*)d_in[2];
    const float* W_ih  = (const float*)d_in[3];
    const float* W_hh  = (const float*)d_in[4];
    const float* b_ih  = (const float*)d_in[5];
    const float* b_hh  = (const float*)d_in[6];
    float* out = (float*)d_out;

    dim3 grid1(T_, 16);
    lstm_xproj_kernel<<<grid1, 128>>>(input, W_ih, b_ih, b_hh);

    lstm_epoch_kernel<<<1, 1>>>();

    const int smem_bytes = (8 * HSK) * sizeof(float);
    cudaFuncSetAttribute(lstm_rec_kernel,
                         cudaFuncAttributeMaxDynamicSharedMemorySize, smem_bytes);
    lstm_rec_kernel<<<NBLK, 512, smem_bytes>>>(h0, c0, W_hh, out);
}

// round 17
// speedup vs baseline: 1.1871x; 1.0441x over previous
#include <cuda_runtime.h>
#include <math.h>
#include <stdint.h>

#define B_   32
#define T_   2048
#define D_   512
#define H_   512
#define G4_  2048
#define NBLK 128
#define XS_  34
#define HSK  516        // hsm row stride (floats); 516 mod 32 = 4

// ---------------- device scratch ----------------------------------------------
__device__ float g_xproj[(size_t)T_ * G4_ * B_];   // [t][g][b]
__device__ __align__(16) float g_h[2][H_ * B_];    // [j][b]  double-buffered
__device__ unsigned g_epoch;
__device__ unsigned g_flags[NBLK * 64];            // one flag per 256B line

// ---------------- helpers -------------------------------------------------------
__device__ __forceinline__ unsigned long long pack2(float lo, float hi) {
    unsigned long long r;
    asm("mov.b64 %0, {%1, %2};" : "=l"(r) : "f"(lo), "f"(hi));
    return r;
}
__device__ __forceinline__ void fma2(unsigned long long& d,
                                     unsigned long long a, unsigned long long b) {
    asm("fma.rn.f32x2 %0, %1, %2, %0;" : "+l"(d) : "l"(a), "l"(b));
}
__device__ __forceinline__ void unpack2(unsigned long long v, float& lo, float& hi) {
    asm("mov.b64 {%0, %1}, %2;" : "=f"(lo), "=f"(hi) : "l"(v));
}
__device__ __forceinline__ unsigned ld_acq(const unsigned* p) {
    unsigned v;
    asm volatile("ld.acquire.gpu.u32 %0, [%1];" : "=r"(v) : "l"(p) : "memory");
    return v;
}
__device__ __forceinline__ void st_rel(unsigned* p, unsigned v) {
    asm volatile("st.release.gpu.u32 [%0], %1;" :: "l"(p), "r"(v) : "memory");
}
__device__ __forceinline__ float tanh_approx(float x) {
    float y;
    asm("tanh.approx.f32 %0, %1;" : "=f"(y) : "f"(x));
    return y;
}
__device__ __forceinline__ float sigmoid_fast(float x) {
    return fmaf(tanh_approx(0.5f * x), 0.5f, 0.5f);
}

__global__ void lstm_epoch_kernel() {
    if (threadIdx.x == 0) g_epoch = g_epoch + 1u;
}

// ---------------- Phase 1: x_proj (measured-best 8g x 4b, unchanged) -----------
__global__ void __launch_bounds__(128, 4) lstm_xproj_kernel(
    const float* __restrict__ input,
    const float* __restrict__ W_ih,
    const float* __restrict__ b_ih,
    const float* __restrict__ b_hh)
{
    __shared__ float ws[128 * 36];
    __shared__ float xs[32 * XS_];

    const int t   = blockIdx.x;
    const int g0  = blockIdx.y * 128;
    const int tid = threadIdx.x;
    const int gg  = tid >> 3;
    const int bg  = tid & 7;

    unsigned long long acc2[16];
#pragma unroll
    for (int v = 0; v < 16; v++) acc2[v] = 0ull;

    for (int kt = 0; kt < 16; kt++) {
        const int k0 = kt * 32;
#pragma unroll
        for (int m = 0; m < 8; m++) {
            int f4 = tid + m * 128;
            int g = f4 >> 3, kq = f4 & 7;
            float4 v = *(const float4*)&W_ih[(size_t)(g0 + g) * D_ + k0 + kq * 4];
            *(float4*)&ws[g * 36 + kq * 4] = v;
        }
#pragma unroll
        for (int m = 0; m < 2; m++) {
            int f4 = tid + m * 128;
            int b = f4 >> 3, kq = f4 & 7;
            float4 v = *(const float4*)&input[((size_t)b * T_ + t) * D_ + k0 + kq * 4];
            xs[(kq * 4 + 0) * XS_ + b] = v.x;
            xs[(kq * 4 + 1) * XS_ + b] = v.y;
            xs[(kq * 4 + 2) * XS_ + b] = v.z;
            xs[(kq * 4 + 3) * XS_ + b] = v.w;
        }
        __syncthreads();

#pragma unroll
        for (int k4 = 0; k4 < 8; k4++) {
            float4 wv[8];
#pragma unroll
            for (int i = 0; i < 8; i++)
                wv[i] = *(const float4*)&ws[(gg + 16 * i) * 36 + k4 * 4];
#pragma unroll
            for (int kk = 0; kk < 4; kk++) {
                const float* xrow = &xs[(k4 * 4 + kk) * XS_ + bg * 4];
                unsigned long long x2a = *(const unsigned long long*)(xrow);
                unsigned long long x2b = *(const unsigned long long*)(xrow + 2);
#pragma unroll
                for (int i = 0; i < 8; i++) {
                    float w = (kk == 0) ? wv[i].x : (kk == 1) ? wv[i].y
                             : (kk == 2) ? wv[i].z : wv[i].w;
                    unsigned long long w2 = pack2(w, w);
                    fma2(acc2[i * 2 + 0], w2, x2a);
                    fma2(acc2[i * 2 + 1], w2, x2b);
                }
            }
        }
        __syncthreads();
    }

#pragma unroll
    for (int i = 0; i < 8; i++) {
        int g = g0 + gg + 16 * i;
        float bias = b_ih[g] + b_hh[g];
        float4 o; float lo, hi;
        unpack2(acc2[i * 2 + 0], lo, hi); o.x = lo + bias; o.y = hi + bias;
        unpack2(acc2[i * 2 + 1], lo, hi); o.z = lo + bias; o.w = hi + bias;
        *(float4*)&g_xproj[((size_t)t * G4_ + g) * B_ + bg * 4] = o;
    }
}

// ---------------- Phase 2: recurrence (JIT warp-local poll+stage) --------------
// 128 blocks = 32 jg x 4 bg, 512 threads. Warp w stages k in [32w, 32w+32)
// (producers jg' = 2w, 2w+1): each lane acquire-polls those two flags, then
// ldcg's its float2s straight into hsm. Detect+read latency pipelines across
// warps; only 2 __syncthreads per step. Butterfly uses 1-shfl select form.
extern "C" __global__ void __launch_bounds__(512, 1) lstm_rec_kernel(
    const float* __restrict__ h0,
    const float* __restrict__ c0,
    const float* __restrict__ W_hh,
    float* __restrict__ out)
{
    extern __shared__ float smem[];
    float* hsm = smem;                         // [8][HSK]  ([b_local][k])

    const int tid  = threadIdx.x;
    const int bid  = blockIdx.x;
    const int jg   = bid >> 2;
    const int bg   = bid & 3;
    const int w    = tid >> 5;                 // local j / stage k-group
    const int lane = tid & 31;
    const int j    = jg * 16 + w;

    // ---- W_hh gate-pair packs (loop-invariant): w2pk[gp*16+kc] ----
    unsigned long long w2pk[32];
#pragma unroll
    for (int gp = 0; gp < 2; gp++) {
        const float* r0 = &W_hh[(size_t)((2 * gp)     * H_ + j) * H_];
        const float* r1 = &W_hh[(size_t)((2 * gp + 1) * H_ + j) * H_];
#pragma unroll
        for (int kc = 0; kc < 16; kc++) {
            int k = lane + 32 * kc;
            w2pk[gp * 16 + kc] = pack2(r0[k], r1[k]);
        }
    }

    const int b_mine = bg * 8 + (lane & 7);
    float creg = c0[(size_t)b_mine * H_ + j];

    const unsigned epoch = *((volatile unsigned*)&g_epoch);
    const unsigned base  = epoch * 4096u;

    const float* xp_base =
        &g_xproj[(size_t)((lane >> 3) * H_ + j) * B_ + b_mine];
    unsigned* my_flag = &g_flags[bid * 64];
    // producers of this warp's staged k range [32w, 32w+32)
    const unsigned* fpa = &g_flags[((2 * w)     * 4 + bg) * 64];
    const unsigned* fpb = &g_flags[((2 * w + 1) * 4 + bg) * 64];

    __syncthreads();

    for (int t = 0; t < T_; t++) {
        // ---- JIT stage: poll own producers, then read k in [32w, 32w+32) ----
        if (t == 0) {
            // h0 is [b][j]; one-time scalar staging
#pragma unroll
            for (int m = 0; m < 4; m++) {
                int idx = m * 512 + tid;       // 0..2047
                int k = idx >> 2, p = idx & 3;
                int b0 = bg * 8 + 2 * p;
                hsm[(2 * p) * HSK + k]     = h0[(size_t)b0 * H_ + k];
                hsm[(2 * p + 1) * HSK + k] = h0[(size_t)(b0 + 1) * H_ + k];
            }
        } else {
            const unsigned tgt = base + (unsigned)t;
            while (ld_acq(fpa) < tgt) { }
            while (ld_acq(fpb) < tgt) { }
            const float* hsrc = g_h[(t - 1) & 1];      // [j][b] flat k*32+b
#pragma unroll
            for (int c = 0; c < 4; c++) {
                int idx = lane + 32 * c;
                int kl = idx >> 2, bp = idx & 3;
                int k = 32 * w + kl;
                float2 v = __ldcg((const float2*)&hsrc[k * B_ + bg * 8 + 2 * bp]);
                hsm[(2 * bp) * HSK + k]     = v.x;
                hsm[(2 * bp + 1) * HSK + k] = v.y;
            }
        }
        float xp = __ldcg(xp_base + (size_t)t * (G4_ * B_));
        __syncthreads();

        // ---- GEMM: gate-pair f32x2, W packs pre-made ----
        unsigned long long acc2[16];
#pragma unroll
        for (int q = 0; q < 16; q++) acc2[q] = 0ull;

#pragma unroll
        for (int kc = 0; kc < 16; kc++) {
            const int k = lane + 32 * kc;
            unsigned long long h2[8];
#pragma unroll
            for (int bl = 0; bl < 8; bl++) {
                float hv = hsm[bl * HSK + k];
                h2[bl] = pack2(hv, hv);
            }
#pragma unroll
            for (int gp = 0; gp < 2; gp++) {
                const unsigned long long w2 = w2pk[gp * 16 + kc];
#pragma unroll
                for (int bl = 0; bl < 8; bl++)
                    fma2(acc2[gp * 8 + bl], w2, h2[bl]);
            }
        }

        // ---- butterfly reduce, 1-shfl select form (31 shfls) ----
        // semantic v[s], s = gate*8+b: gate0=acc2[b].lo gate1=acc2[b].hi
        //                              gate2=acc2[8+b].lo gate3=acc2[8+b].hi
        float v16[16];
#pragma unroll
        for (int b = 0; b < 8; b++) {
            float alo, ahi, blo, bhi;
            unpack2(acc2[b],     alo, ahi);    // gates 0,1
            unpack2(acc2[8 + b], blo, bhi);    // gates 2,3
            // pair (v[b]=alo, v[b+16]=blo): keep sel, fetch partner's anti-sel
            float sel  = (lane & 16) ? blo : alo;
            float asel = (lane & 16) ? alo : blo;
            v16[b] = sel + __shfl_xor_sync(0xffffffffu, asel, 16);
            sel  = (lane & 16) ? bhi : ahi;    // pair (v[8+b]=ahi, v[24+b]=bhi)
            asel = (lane & 16) ? ahi : bhi;
            v16[8 + b] = sel + __shfl_xor_sync(0xffffffffu, asel, 16);
        }
#pragma unroll
        for (int s = 0; s < 8; s++) {
            float sel  = (lane & 8) ? v16[s + 8] : v16[s];
            float asel = (lane & 8) ? v16[s] : v16[s + 8];
            v16[s] = sel + __shfl_xor_sync(0xffffffffu, asel, 8);
        }
#pragma unroll
        for (int s = 0; s < 4; s++) {
            float sel  = (lane & 4) ? v16[s + 4] : v16[s];
            float asel = (lane & 4) ? v16[s] : v16[s + 4];
            v16[s] = sel + __shfl_xor_sync(0xffffffffu, asel, 4);
        }
#pragma unroll
        for (int s = 0; s < 2; s++) {
            float sel  = (lane & 2) ? v16[s + 2] : v16[s];
            float asel = (lane & 2) ? v16[s] : v16[s + 2];
            v16[s] = sel + __shfl_xor_sync(0xffffffffu, asel, 2);
        }
        {
            float sel  = (lane & 1) ? v16[1] : v16[0];
            float asel = (lane & 1) ? v16[0] : v16[1];
            v16[0] = sel + __shfl_xor_sync(0xffffffffu, asel, 1);
        }
        float pre = v16[0] + xp;   // lane L: gate L>>3, batch bg*8+(L&7)

        // ---- in-warp activations ----
        float xf = __shfl_down_sync(0xffffffffu, pre, 8);
        float xg = __shfl_down_sync(0xffffffffu, pre, 16);
        float xo = __shfl_down_sync(0xffffffffu, pre, 24);
        float iv = sigmoid_fast(pre);
        float fv = sigmoid_fast(xf);
        float gv = tanh_approx(xg);
        float ov = sigmoid_fast(xo);
        float cn = fv * creg + iv * gv;
        float hn = ov * tanh_approx(cn);
        if (lane < 8) {
            creg = cn;
            __stcg(&g_h[t & 1][(size_t)j * B_ + b_mine], hn);   // [j][b]
            if (t == T_ - 1) {
                out[(size_t)b_mine * H_ + j]           = hn;    // [b][j]
                out[(size_t)B_ * H_ + b_mine * H_ + j] = cn;
            }
        }
        __syncthreads();   // all warps' h stores + hsm reads done
        if (tid == 0) st_rel(my_flag, base + (unsigned)t + 1u);
        // next step's per-warp JIT polls provide the inter-block sync
    }
}

// ---------------- launch ------------------------------------------------------
extern "C" void kernel_launch(void* const* d_in, const int* in_sizes, int n_in,
                              void* d_out, int out_size)
{
    const float* input = (const float*)d_in[0];
    const float* h0    = (const float*)d_in[1];
    const float* c0    = (const float*)d_in[2];
    const float* W_ih  = (const float*)d_in[3];
    const float* W_hh  = (const float*)d_in[4];
    const float* b_ih  = (const float*)d_in[5];
    const float* b_hh  = (const float*)d_in[6];
    float* out = (float*)d_out;

    dim3 grid1(T_, 16);
    lstm_xproj_kernel<<<grid1, 128>>>(input, W_ih, b_ih, b_hh);

    lstm_epoch_kernel<<<1, 1>>>();

    const int smem_bytes = (8 * HSK) * sizeof(float);
    cudaFuncSetAttribute(lstm_rec_kernel,
                         cudaFuncAttributeMaxDynamicSharedMemorySize, smem_bytes);
    lstm_rec_kernel<<<NBLK, 512, smem_bytes>>>(h0, c0, W_hh, out);
}